// round 16
// baseline (speedup 1.0000x reference)
#include <cuda_runtime.h>
#include <cstdint>

#define N_CELL 200000
#define N_WELL 2000
#define E_CC   1200000
#define E_CW   200000
#define CF     16
#define WF     8
#define H      128
#define OUT    75
#define WPB    8
#define R      16

// ---------------- device scratch ----------------
// INVARIANT: g_aggx, g_cnt, g_Ur, g_Vr, g_meta are ZERO at kernel_launch entry.
// True at first call (module-load zero-init); maintained by tail-zeroing at the
// end of every call, after their consumers finish. Deterministic per call.
__device__ __align__(16) float g_aggx[(size_t)N_CELL * CF];
__device__ int      g_cnt[N_CELL];
// g_bm is replay-invariant: k_mark's atomicOr sets the same bits every call.
__device__ unsigned g_bm[(N_CELL + 31) / 32];
__device__ __align__(16) float g_Ur[(size_t)R * N_WELL * CF];
__device__ __align__(16) float g_Vr[(size_t)R * N_WELL * CF];
__device__ __align__(16) float g_meta[(size_t)R * N_WELL * 4];   // {beta, count, 0, 0}

// fused-weight table
// F rows: [0,16) M1 (Un), [16,32) M2 (Vn), 32 v1 (beta_n), 33 v2 (mask),
//         [34,42) M3 (wx), 42 v3 (const)
__device__ float g_F[43 * H];

__device__ __forceinline__ void red4(float* p, float a, float b, float c, float d) {
    asm volatile("red.global.add.v4.f32 [%0], {%1,%2,%3,%4};"
                 :: "l"(p), "f"(a), "f"(b), "f"(c), "f"(d) : "memory");
}

// ---------------- zero kernels (run at graph TAIL) ----------------
__global__ void k_zero_cell() {           // aggx + cnt
    int i = blockIdx.x * blockDim.x + threadIdx.x;
    if (i < N_CELL * CF / 4) ((float4*)g_aggx)[i] = make_float4(0.f, 0.f, 0.f, 0.f);
    if (i < N_CELL) g_cnt[i] = 0;
}
__global__ void k_zero_well() {           // Ur + Vr + meta
    int i = blockIdx.x * blockDim.x + threadIdx.x;
    if (i < R * N_WELL * CF / 4) {
        ((float4*)g_Ur)[i] = make_float4(0.f, 0.f, 0.f, 0.f);
        ((float4*)g_Vr)[i] = make_float4(0.f, 0.f, 0.f, 0.f);
    }
    if (i < R * N_WELL) ((float4*)g_meta)[i] = make_float4(0.f, 0.f, 0.f, 0.f);
}

// ---------------- mark active cells (idempotent) ----------------
__global__ void k_mark(const int* __restrict__ ews) {
    int e = blockIdx.x * blockDim.x + threadIdx.x;
    if (e >= E_CW) return;
    int s = __ldg(&ews[e]);
    atomicOr(&g_bm[s >> 5], 1u << (s & 31));
}

// ---------------- single-kernel fuse chain ----------------
__device__ __forceinline__ void mmrow(const float* sIn, const float* __restrict__ M,
                                      float* sOut, float* gOut,
                                      const float* __restrict__ addv, float* sP)
{
    int tid  = threadIdx.x;
    int h    = tid & (H - 1);
    int half = tid >> 7;
    float acc = 0.f;
    int k0 = half * 64;
#pragma unroll 16
    for (int k = 0; k < 64; k++)
        acc += sIn[k0 + k] * __ldg(&M[(k0 + k) * H + h]);
    __syncthreads();
    sP[tid] = acc;
    __syncthreads();
    if (half == 0) {
        float v = sP[h] + sP[h + 128];
        if (addv) v += __ldg(&addv[h]);
        if (sOut) sOut[h] = v;
        if (gOut) gOut[h] = v;
    }
    __syncthreads();
}

__global__ void __launch_bounds__(256) k_fuse(
    const float* __restrict__ W_cell, const float* __restrict__ b_cell,
    const float* __restrict__ Wl_cc, const float* __restrict__ Wr_cc,
    const float* __restrict__ bl_cc,
    const float* __restrict__ W_well, const float* __restrict__ b_well,
    const float* __restrict__ Wl_cw, const float* __restrict__ bl_cw,
    const float* __restrict__ Wr_cw,
    const float* __restrict__ Wm1,   const float* __restrict__ bm1)
{
    __shared__ float sA[H], sB[H], sP[256];
    int r   = blockIdx.x;
    int tid = threadIdx.x;
    int h   = tid & (H - 1);

    const float* L; const float* M; const float* A1 = nullptr;
    if (r < 16)      { L = W_cell + r * H;        M = Wl_cc; }
    else if (r < 32) { L = W_cell + (r - 16) * H; M = Wr_cc; }
    else if (r == 32){ L = b_cell;                M = Wl_cc; }
    else if (r == 33){ L = b_cell;                M = Wr_cc; A1 = bl_cc; }
    else if (r < 42) { L = W_well + (r - 34) * H; M = Wr_cw; }
    else             { L = b_well;                M = Wr_cw; A1 = bl_cw; }

    if (tid < H) sA[h] = __ldg(&L[h]);
    __syncthreads();

    mmrow(sA, M, sB, nullptr, A1, sP);

    const float* last = sB;
    if (r < 34) {
        mmrow(sB, Wl_cw, sA, nullptr, nullptr, sP);
        last = sA;
    }
    mmrow(last, Wm1, nullptr, g_F + r * H, (r == 42) ? bm1 : nullptr, sP);
}

// ---- K3: cc scan (measured-best body, unchanged) ----
__global__ void __launch_bounds__(256) k_cc(const int* __restrict__ ei,
                                            const float* __restrict__ x) {
    int t = blockIdx.x * blockDim.x + threadIdx.x;
    if (t >= E_CC / 2) return;

    int2 dv = __ldg((const int2*)(ei + E_CC) + t);
    int2 sv = __ldg((const int2*)ei + t);

    bool h0 = (__ldg(&g_bm[dv.x >> 5]) >> (dv.x & 31)) & 1u;
    bool h1 = (__ldg(&g_bm[dv.y >> 5]) >> (dv.y & 31)) & 1u;

    float4 a0, a1, a2, a3, c0, c1, c2, c3;
    if (h0) {
        const float4* xp = (const float4*)(x + (size_t)sv.x * CF);
        a0 = __ldg(xp + 0); a1 = __ldg(xp + 1); a2 = __ldg(xp + 2); a3 = __ldg(xp + 3);
    }
    if (h1) {
        const float4* xp = (const float4*)(x + (size_t)sv.y * CF);
        c0 = __ldg(xp + 0); c1 = __ldg(xp + 1); c2 = __ldg(xp + 2); c3 = __ldg(xp + 3);
    }
    if (h0) {
        float* ap = g_aggx + (size_t)dv.x * CF;
        red4(ap + 0,  a0.x, a0.y, a0.z, a0.w);
        red4(ap + 4,  a1.x, a1.y, a1.z, a1.w);
        red4(ap + 8,  a2.x, a2.y, a2.z, a2.w);
        red4(ap + 12, a3.x, a3.y, a3.z, a3.w);
        atomicAdd(&g_cnt[dv.x], 1);
    }
    if (h1) {
        float* ap = g_aggx + (size_t)dv.y * CF;
        red4(ap + 0,  c0.x, c0.y, c0.z, c0.w);
        red4(ap + 4,  c1.x, c1.y, c1.z, c1.w);
        red4(ap + 8,  c2.x, c2.y, c2.z, c2.w);
        red4(ap + 12, c3.x, c3.y, c3.z, c3.w);
        atomicAdd(&g_cnt[dv.y], 1);
    }
}

// ---- cwV: 2 edges/thread, int2 loads, front-batched gathers (side stream) ----
__global__ void __launch_bounds__(256) k_cwV(const int* __restrict__ ews,
                                             const int* __restrict__ ewd,
                                             const float* __restrict__ x) {
    int t = blockIdx.x * blockDim.x + threadIdx.x;
    if (t >= E_CW / 2) return;
    int rep = blockIdx.x & (R - 1);

    int2 sv = __ldg((const int2*)ews + t);
    int2 wv = __ldg((const int2*)ewd + t);

    const float4* xp0 = (const float4*)(x + (size_t)sv.x * CF);
    const float4* xp1 = (const float4*)(x + (size_t)sv.y * CF);
    float4 b0 = __ldg(xp0 + 0), b1 = __ldg(xp0 + 1), b2 = __ldg(xp0 + 2), b3 = __ldg(xp0 + 3);
    float4 d0 = __ldg(xp1 + 0), d1 = __ldg(xp1 + 1), d2 = __ldg(xp1 + 2), d3 = __ldg(xp1 + 3);

    float* V0 = g_Vr + ((size_t)rep * N_WELL + wv.x) * CF;
    red4(V0 + 0,  b0.x, b0.y, b0.z, b0.w);
    red4(V0 + 4,  b1.x, b1.y, b1.z, b1.w);
    red4(V0 + 8,  b2.x, b2.y, b2.z, b2.w);
    red4(V0 + 12, b3.x, b3.y, b3.z, b3.w);
    red4(g_meta + ((size_t)rep * N_WELL + wv.x) * 4, 0.f, 1.f, 0.f, 0.f);

    float* V1 = g_Vr + ((size_t)rep * N_WELL + wv.y) * CF;
    red4(V1 + 0,  d0.x, d0.y, d0.z, d0.w);
    red4(V1 + 4,  d1.x, d1.y, d1.z, d1.w);
    red4(V1 + 8,  d2.x, d2.y, d2.z, d2.w);
    red4(V1 + 12, d3.x, d3.y, d3.z, d3.w);
    red4(g_meta + ((size_t)rep * N_WELL + wv.y) * 4, 0.f, 1.f, 0.f, 0.f);
}

// ---- cwU: 2 edges/thread, int2 loads, front-batched gathers (critical path) ----
__global__ void __launch_bounds__(256) k_cwU(const int* __restrict__ ews,
                                             const int* __restrict__ ewd) {
    int t = blockIdx.x * blockDim.x + threadIdx.x;
    if (t >= E_CW / 2) return;
    int rep = blockIdx.x & (R - 1);

    int2 sv = __ldg((const int2*)ews + t);
    int2 wv = __ldg((const int2*)ewd + t);

    int c0 = __ldg(&g_cnt[sv.x]);
    int c1 = __ldg(&g_cnt[sv.y]);

    const float4* ap0 = (const float4*)(g_aggx + (size_t)sv.x * CF);
    const float4* ap1 = (const float4*)(g_aggx + (size_t)sv.y * CF);
    float4 a0 = __ldg(ap0 + 0), a1 = __ldg(ap0 + 1), a2 = __ldg(ap0 + 2), a3 = __ldg(ap0 + 3);
    float4 e0 = __ldg(ap1 + 0), e1 = __ldg(ap1 + 1), e2 = __ldg(ap1 + 2), e3 = __ldg(ap1 + 3);

    float inv0 = (c0 > 0) ? (1.f / (float)c0) : 0.f;
    float inv1 = (c1 > 0) ? (1.f / (float)c1) : 0.f;

    float* U0 = g_Ur + ((size_t)rep * N_WELL + wv.x) * CF;
    red4(U0 + 0,  a0.x * inv0, a0.y * inv0, a0.z * inv0, a0.w * inv0);
    red4(U0 + 4,  a1.x * inv0, a1.y * inv0, a1.z * inv0, a1.w * inv0);
    red4(U0 + 8,  a2.x * inv0, a2.y * inv0, a2.z * inv0, a2.w * inv0);
    red4(U0 + 12, a3.x * inv0, a3.y * inv0, a3.z * inv0, a3.w * inv0);
    red4(g_meta + ((size_t)rep * N_WELL + wv.x) * 4, (c0 > 0) ? 1.f : 0.f, 0.f, 0.f, 0.f);

    float* U1 = g_Ur + ((size_t)rep * N_WELL + wv.y) * CF;
    red4(U1 + 0,  e0.x * inv1, e0.y * inv1, e0.z * inv1, e0.w * inv1);
    red4(U1 + 4,  e1.x * inv1, e1.y * inv1, e1.z * inv1, e1.w * inv1);
    red4(U1 + 8,  e2.x * inv1, e2.y * inv1, e2.z * inv1, e2.w * inv1);
    red4(U1 + 12, e3.x * inv1, e3.y * inv1, e3.z * inv1, e3.w * inv1);
    red4(g_meta + ((size_t)rep * N_WELL + wv.y) * 4, (c1 > 0) ? 1.f : 0.f, 0.f, 0.f, 0.f);
}

// ---------------- K6: per-well head (unchanged) ----------------
__global__ void __launch_bounds__(H) k_well(
    const float* __restrict__ well_x,
    const float* __restrict__ Wm2, const float* __restrict__ bm2,
    float* __restrict__ out)
{
    __shared__ __align__(16) float sm[H][WPB];
    __shared__ float sUn[WPB][CF], sVn[WPB][CF], sWX[WPB][WF];
    __shared__ float sb1[WPB], sb2[WPB], sinv[WPB];

    int h  = threadIdx.x;
    int w0 = blockIdx.x * WPB;

    if (h < WPB) {
        float beta = 0.f, cw = 0.f;
#pragma unroll
        for (int r = 0; r < R; r++) {
            const float* mp = g_meta + ((size_t)r * N_WELL + (w0 + h)) * 4;
            beta += mp[0];
            cw   += mp[1];
        }
        float inv = 1.f / fmaxf(cw, 1.f);
        sinv[h] = inv;
        sb1[h]  = beta * inv;
        sb2[h]  = (cw > 0.5f) ? 1.f : 0.f;
    }
    __syncthreads();
    {
        int t = h >> 4, j = h & 15;
        float su = 0.f, svv = 0.f;
#pragma unroll
        for (int r = 0; r < R; r++) {
            size_t off = ((size_t)r * N_WELL + (w0 + t)) * CF + j;
            su  += g_Ur[off];
            svv += g_Vr[off];
        }
        sUn[t][j] = su * sinv[t];
        sVn[t][j] = svv * sinv[t];
    }
    if (h < WPB * WF) {
        int t = h >> 3, j = h & 7;
        sWX[t][j] = __ldg(&well_x[(w0 + t) * WF + j]);
    }
    __syncthreads();

    float acc[WPB];
    {
        float f1 = g_F[32 * H + h], f2 = g_F[33 * H + h], f3 = g_F[42 * H + h];
#pragma unroll
        for (int t = 0; t < WPB; t++) acc[t] = f3 + sb1[t] * f1 + sb2[t] * f2;
    }
#pragma unroll
    for (int j = 0; j < CF; j++) {
        float m1 = g_F[j * H + h];
        float m2 = g_F[(16 + j) * H + h];
#pragma unroll
        for (int t = 0; t < WPB; t++) acc[t] += sUn[t][j] * m1 + sVn[t][j] * m2;
    }
#pragma unroll
    for (int j = 0; j < WF; j++) {
        float m3 = g_F[(34 + j) * H + h];
#pragma unroll
        for (int t = 0; t < WPB; t++) acc[t] += sWX[t][j] * m3;
    }
#pragma unroll
    for (int t = 0; t < WPB; t++) sm[h][t] = fmaxf(acc[t], 0.f);
    __syncthreads();

    if (h < OUT) {
        float o[WPB];
        float bv = __ldg(&bm2[h]);
#pragma unroll
        for (int t = 0; t < WPB; t++) o[t] = bv;
#pragma unroll 4
        for (int k = 0; k < H; k++) {
            float wm = __ldg(&Wm2[k * OUT + h]);
            float4 p0 = *(const float4*)&sm[k][0];
            float4 p1 = *(const float4*)&sm[k][4];
            o[0] += p0.x * wm;  o[1] += p0.y * wm;
            o[2] += p0.z * wm;  o[3] += p0.w * wm;
            o[4] += p1.x * wm;  o[5] += p1.y * wm;
            o[6] += p1.z * wm;  o[7] += p1.w * wm;
        }
#pragma unroll
        for (int t = 0; t < WPB; t++) out[(w0 + t) * OUT + h] = o[t];
    }
}

// ---------------- launch (tail-zeroing; mark on main head) ----------------
static cudaStream_t s1;
static cudaEvent_t evRoot, evV, evU, evW, evEnd;
static bool g_host_init = false;

extern "C" void kernel_launch(void* const* d_in, const int* in_sizes, int n_in,
                              void* d_out, int out_size)
{
    if (!g_host_init) {
        cudaStreamCreateWithFlags(&s1, cudaStreamNonBlocking);
        cudaEventCreateWithFlags(&evRoot, cudaEventDisableTiming);
        cudaEventCreateWithFlags(&evV, cudaEventDisableTiming);
        cudaEventCreateWithFlags(&evU, cudaEventDisableTiming);
        cudaEventCreateWithFlags(&evW, cudaEventDisableTiming);
        cudaEventCreateWithFlags(&evEnd, cudaEventDisableTiming);
        g_host_init = true;
    }

    const float* cell_x  = (const float*)d_in[0];
    const float* well_x  = (const float*)d_in[1];
    const int*   ei_cell = (const int*)  d_in[2];
    const int*   ews     = (const int*)  d_in[3];
    const int*   ewd     = (const int*)  d_in[4];
    const float* W_cell  = (const float*)d_in[5];
    const float* b_cell  = (const float*)d_in[6];
    const float* W_well  = (const float*)d_in[7];
    const float* b_well  = (const float*)d_in[8];
    const float* Wl_cc   = (const float*)d_in[9];
    const float* bl_cc   = (const float*)d_in[10];
    const float* Wr_cc   = (const float*)d_in[11];
    const float* Wl_cw   = (const float*)d_in[12];
    const float* bl_cw   = (const float*)d_in[13];
    const float* Wr_cw   = (const float*)d_in[14];
    const float* W_m1    = (const float*)d_in[15];
    const float* b_m1    = (const float*)d_in[16];
    const float* W_m2    = (const float*)d_in[17];
    const float* b_m2    = (const float*)d_in[18];
    float* out = (float*)d_out;

    // fork
    cudaEventRecord(evRoot, 0);
    cudaStreamWaitEvent(s1, evRoot, 0);

    // side stream: fuse -> cwV (scratch already zero at entry)
    k_fuse<<<43, 256, 0, s1>>>(W_cell, b_cell, Wl_cc, Wr_cc, bl_cc,
                               W_well, b_well, Wl_cw, bl_cw, Wr_cw,
                               W_m1, b_m1);
    k_cwV<<<(E_CW / 2 + 255) / 256, 256, 0, s1>>>(ews, ewd, cell_x);
    cudaEventRecord(evV, s1);

    // main stream: mark -> cc -> cwU -> well
    k_mark<<<(E_CW + 255) / 256, 256>>>(ews);
    k_cc<<<(E_CC / 2 + 255) / 256, 256>>>(ei_cell, cell_x);
    cudaStreamWaitEvent(0, evV, 0);
    k_cwU<<<(E_CW / 2 + 255) / 256, 256>>>(ews, ewd);
    cudaEventRecord(evU, 0);                       // aggx/cnt fully consumed
    k_well<<<N_WELL / WPB, H>>>(well_x, W_m2, b_m2, out);
    cudaEventRecord(evW, 0);                       // Ur/Vr/meta fully consumed

    // tail: restore the zero-invariant on the side stream, overlapped with well
    cudaStreamWaitEvent(s1, evU, 0);
    k_zero_cell<<<(N_CELL * CF / 4 + 255) / 256, 256, 0, s1>>>();
    cudaStreamWaitEvent(s1, evW, 0);
    k_zero_well<<<(R * N_WELL * CF / 4 + 255) / 256, 256, 0, s1>>>();
    cudaEventRecord(evEnd, s1);
    cudaStreamWaitEvent(0, evEnd, 0);              // join for valid capture
}

// round 17
// speedup vs baseline: 1.0607x; 1.0607x over previous
#include <cuda_runtime.h>
#include <cstdint>

#define N_CELL 200000
#define N_WELL 2000
#define E_CC   1200000
#define E_CW   200000
#define CF     16
#define WF     8
#define H      128
#define OUT    75
#define WPB    8
#define R      16

// ---------------- device scratch ----------------
// INVARIANT: g_aggx, g_cnt, g_Ur, g_Vr, g_meta are ZERO at kernel_launch entry.
// aggx/cnt restored by tail k_zero_cell; Ur/Vr/meta restored inside k_well
// (each block zeroes exactly the slices it consumed). Deterministic per call.
__device__ __align__(16) float g_aggx[(size_t)N_CELL * CF];
__device__ int      g_cnt[N_CELL];
// g_bm is replay-invariant: k_mark's atomicOr sets the same bits every call.
__device__ unsigned g_bm[(N_CELL + 31) / 32];
__device__ __align__(16) float g_Ur[(size_t)R * N_WELL * CF];
__device__ __align__(16) float g_Vr[(size_t)R * N_WELL * CF];
__device__ __align__(16) float g_meta[(size_t)R * N_WELL * 4];   // {beta, count, 0, 0}

// fused-weight table
// F rows: [0,16) M1 (Un), [16,32) M2 (Vn), 32 v1 (beta_n), 33 v2 (mask),
//         [34,42) M3 (wx), 42 v3 (const)
__device__ float g_F[43 * H];

__device__ __forceinline__ void red4(float* p, float a, float b, float c, float d) {
    asm volatile("red.global.add.v4.f32 [%0], {%1,%2,%3,%4};"
                 :: "l"(p), "f"(a), "f"(b), "f"(c), "f"(d) : "memory");
}

// ---------------- tail zero (aggx + cnt only) ----------------
__global__ void k_zero_cell() {
    int i = blockIdx.x * blockDim.x + threadIdx.x;
    if (i < N_CELL * CF / 4) ((float4*)g_aggx)[i] = make_float4(0.f, 0.f, 0.f, 0.f);
    if (i < N_CELL) g_cnt[i] = 0;
}

// ---------------- mark active cells (idempotent) ----------------
__global__ void k_mark(const int* __restrict__ ews) {
    int e = blockIdx.x * blockDim.x + threadIdx.x;
    if (e >= E_CW) return;
    int s = __ldg(&ews[e]);
    atomicOr(&g_bm[s >> 5], 1u << (s & 31));
}

// ---------------- fuse row pipeline (block-local) ----------------
__device__ __forceinline__ void mmrow(const float* sIn, const float* __restrict__ M,
                                      float* sOut, float* gOut,
                                      const float* __restrict__ addv, float* sP)
{
    int tid  = threadIdx.x;
    int h    = tid & (H - 1);
    int half = tid >> 7;
    float acc = 0.f;
    int k0 = half * 64;
#pragma unroll 16
    for (int k = 0; k < 64; k++)
        acc += sIn[k0 + k] * __ldg(&M[(k0 + k) * H + h]);
    __syncthreads();
    sP[tid] = acc;
    __syncthreads();
    if (half == 0) {
        float v = sP[h] + sP[h + 128];
        if (addv) v += __ldg(&addv[h]);
        if (sOut) sOut[h] = v;
        if (gOut) gOut[h] = v;
    }
    __syncthreads();
}

// ---------------- combined side kernel: fuse (blocks<43) + cwV (rest) -------
#define CWV_BLOCKS ((E_CW / 2 + 255) / 256)

__global__ void __launch_bounds__(256) k_side(
    const float* __restrict__ W_cell, const float* __restrict__ b_cell,
    const float* __restrict__ Wl_cc, const float* __restrict__ Wr_cc,
    const float* __restrict__ bl_cc,
    const float* __restrict__ W_well, const float* __restrict__ b_well,
    const float* __restrict__ Wl_cw, const float* __restrict__ bl_cw,
    const float* __restrict__ Wr_cw,
    const float* __restrict__ Wm1,   const float* __restrict__ bm1,
    const int* __restrict__ ews,     const int* __restrict__ ewd,
    const float* __restrict__ x)
{
    if (blockIdx.x < 43) {
        __shared__ float sA[H], sB[H], sP[256];
        int r   = blockIdx.x;
        int tid = threadIdx.x;
        int h   = tid & (H - 1);

        const float* L; const float* M; const float* A1 = nullptr;
        if (r < 16)      { L = W_cell + r * H;        M = Wl_cc; }
        else if (r < 32) { L = W_cell + (r - 16) * H; M = Wr_cc; }
        else if (r == 32){ L = b_cell;                M = Wl_cc; }
        else if (r == 33){ L = b_cell;                M = Wr_cc; A1 = bl_cc; }
        else if (r < 42) { L = W_well + (r - 34) * H; M = Wr_cw; }
        else             { L = b_well;                M = Wr_cw; A1 = bl_cw; }

        if (tid < H) sA[h] = __ldg(&L[h]);
        __syncthreads();

        mmrow(sA, M, sB, nullptr, A1, sP);
        const float* last = sB;
        if (r < 34) {
            mmrow(sB, Wl_cw, sA, nullptr, nullptr, sP);
            last = sA;
        }
        mmrow(last, Wm1, nullptr, g_F + r * H, (r == 42) ? bm1 : nullptr, sP);
        return;
    }

    // ---- cwV half: 2 edges/thread ----
    int blk = blockIdx.x - 43;
    int t = blk * blockDim.x + threadIdx.x;
    if (t >= E_CW / 2) return;
    int rep = blk & (R - 1);

    int2 sv = __ldg((const int2*)ews + t);
    int2 wv = __ldg((const int2*)ewd + t);

    const float4* xp0 = (const float4*)(x + (size_t)sv.x * CF);
    const float4* xp1 = (const float4*)(x + (size_t)sv.y * CF);
    float4 b0 = __ldg(xp0 + 0), b1 = __ldg(xp0 + 1), b2 = __ldg(xp0 + 2), b3 = __ldg(xp0 + 3);
    float4 d0 = __ldg(xp1 + 0), d1 = __ldg(xp1 + 1), d2 = __ldg(xp1 + 2), d3 = __ldg(xp1 + 3);

    float* V0 = g_Vr + ((size_t)rep * N_WELL + wv.x) * CF;
    red4(V0 + 0,  b0.x, b0.y, b0.z, b0.w);
    red4(V0 + 4,  b1.x, b1.y, b1.z, b1.w);
    red4(V0 + 8,  b2.x, b2.y, b2.z, b2.w);
    red4(V0 + 12, b3.x, b3.y, b3.z, b3.w);
    red4(g_meta + ((size_t)rep * N_WELL + wv.x) * 4, 0.f, 1.f, 0.f, 0.f);

    float* V1 = g_Vr + ((size_t)rep * N_WELL + wv.y) * CF;
    red4(V1 + 0,  d0.x, d0.y, d0.z, d0.w);
    red4(V1 + 4,  d1.x, d1.y, d1.z, d1.w);
    red4(V1 + 8,  d2.x, d2.y, d2.z, d2.w);
    red4(V1 + 12, d3.x, d3.y, d3.z, d3.w);
    red4(g_meta + ((size_t)rep * N_WELL + wv.y) * 4, 0.f, 1.f, 0.f, 0.f);
}

// ---- K3: cc scan (measured-best body, unchanged) ----
__global__ void __launch_bounds__(256) k_cc(const int* __restrict__ ei,
                                            const float* __restrict__ x) {
    int t = blockIdx.x * blockDim.x + threadIdx.x;
    if (t >= E_CC / 2) return;

    int2 dv = __ldg((const int2*)(ei + E_CC) + t);
    int2 sv = __ldg((const int2*)ei + t);

    bool h0 = (__ldg(&g_bm[dv.x >> 5]) >> (dv.x & 31)) & 1u;
    bool h1 = (__ldg(&g_bm[dv.y >> 5]) >> (dv.y & 31)) & 1u;

    float4 a0, a1, a2, a3, c0, c1, c2, c3;
    if (h0) {
        const float4* xp = (const float4*)(x + (size_t)sv.x * CF);
        a0 = __ldg(xp + 0); a1 = __ldg(xp + 1); a2 = __ldg(xp + 2); a3 = __ldg(xp + 3);
    }
    if (h1) {
        const float4* xp = (const float4*)(x + (size_t)sv.y * CF);
        c0 = __ldg(xp + 0); c1 = __ldg(xp + 1); c2 = __ldg(xp + 2); c3 = __ldg(xp + 3);
    }
    if (h0) {
        float* ap = g_aggx + (size_t)dv.x * CF;
        red4(ap + 0,  a0.x, a0.y, a0.z, a0.w);
        red4(ap + 4,  a1.x, a1.y, a1.z, a1.w);
        red4(ap + 8,  a2.x, a2.y, a2.z, a2.w);
        red4(ap + 12, a3.x, a3.y, a3.z, a3.w);
        atomicAdd(&g_cnt[dv.x], 1);
    }
    if (h1) {
        float* ap = g_aggx + (size_t)dv.y * CF;
        red4(ap + 0,  c0.x, c0.y, c0.z, c0.w);
        red4(ap + 4,  c1.x, c1.y, c1.z, c1.w);
        red4(ap + 8,  c2.x, c2.y, c2.z, c2.w);
        red4(ap + 12, c3.x, c3.y, c3.z, c3.w);
        atomicAdd(&g_cnt[dv.y], 1);
    }
}

// ---- cwU: 2 edges/thread (unchanged) ----
__global__ void __launch_bounds__(256) k_cwU(const int* __restrict__ ews,
                                             const int* __restrict__ ewd) {
    int t = blockIdx.x * blockDim.x + threadIdx.x;
    if (t >= E_CW / 2) return;
    int rep = blockIdx.x & (R - 1);

    int2 sv = __ldg((const int2*)ews + t);
    int2 wv = __ldg((const int2*)ewd + t);

    int c0 = __ldg(&g_cnt[sv.x]);
    int c1 = __ldg(&g_cnt[sv.y]);

    const float4* ap0 = (const float4*)(g_aggx + (size_t)sv.x * CF);
    const float4* ap1 = (const float4*)(g_aggx + (size_t)sv.y * CF);
    float4 a0 = __ldg(ap0 + 0), a1 = __ldg(ap0 + 1), a2 = __ldg(ap0 + 2), a3 = __ldg(ap0 + 3);
    float4 e0 = __ldg(ap1 + 0), e1 = __ldg(ap1 + 1), e2 = __ldg(ap1 + 2), e3 = __ldg(ap1 + 3);

    float inv0 = (c0 > 0) ? (1.f / (float)c0) : 0.f;
    float inv1 = (c1 > 0) ? (1.f / (float)c1) : 0.f;

    float* U0 = g_Ur + ((size_t)rep * N_WELL + wv.x) * CF;
    red4(U0 + 0,  a0.x * inv0, a0.y * inv0, a0.z * inv0, a0.w * inv0);
    red4(U0 + 4,  a1.x * inv0, a1.y * inv0, a1.z * inv0, a1.w * inv0);
    red4(U0 + 8,  a2.x * inv0, a2.y * inv0, a2.z * inv0, a2.w * inv0);
    red4(U0 + 12, a3.x * inv0, a3.y * inv0, a3.z * inv0, a3.w * inv0);
    red4(g_meta + ((size_t)rep * N_WELL + wv.x) * 4, (c0 > 0) ? 1.f : 0.f, 0.f, 0.f, 0.f);

    float* U1 = g_Ur + ((size_t)rep * N_WELL + wv.y) * CF;
    red4(U1 + 0,  e0.x * inv1, e0.y * inv1, e0.z * inv1, e0.w * inv1);
    red4(U1 + 4,  e1.x * inv1, e1.y * inv1, e1.z * inv1, e1.w * inv1);
    red4(U1 + 8,  e2.x * inv1, e2.y * inv1, e2.z * inv1, e2.w * inv1);
    red4(U1 + 12, e3.x * inv1, e3.y * inv1, e3.z * inv1, e3.w * inv1);
    red4(g_meta + ((size_t)rep * N_WELL + wv.y) * 4, (c1 > 0) ? 1.f : 0.f, 0.f, 0.f, 0.f);
}

// ---------------- K6: per-well head + self-zeroing of consumed slices -------
__global__ void __launch_bounds__(H) k_well(
    const float* __restrict__ well_x,
    const float* __restrict__ Wm2, const float* __restrict__ bm2,
    float* __restrict__ out)
{
    __shared__ __align__(16) float sm[H][WPB];
    __shared__ float sUn[WPB][CF], sVn[WPB][CF], sWX[WPB][WF];
    __shared__ float sb1[WPB], sb2[WPB], sinv[WPB];

    int h  = threadIdx.x;
    int w0 = blockIdx.x * WPB;

    if (h < WPB) {
        float beta = 0.f, cw = 0.f;
#pragma unroll
        for (int r = 0; r < R; r++) {
            const float* mp = g_meta + ((size_t)r * N_WELL + (w0 + h)) * 4;
            beta += mp[0];
            cw   += mp[1];
        }
        float inv = 1.f / fmaxf(cw, 1.f);
        sinv[h] = inv;
        sb1[h]  = beta * inv;
        sb2[h]  = (cw > 0.5f) ? 1.f : 0.f;
    }
    __syncthreads();
    {
        int t = h >> 4, j = h & 15;
        float su = 0.f, svv = 0.f;
#pragma unroll
        for (int r = 0; r < R; r++) {
            size_t off = ((size_t)r * N_WELL + (w0 + t)) * CF + j;
            su  += g_Ur[off];
            svv += g_Vr[off];
        }
        sUn[t][j] = su * sinv[t];
        sVn[t][j] = svv * sinv[t];
    }
    if (h < WPB * WF) {
        int t = h >> 3, j = h & 7;
        sWX[t][j] = __ldg(&well_x[(w0 + t) * WF + j]);
    }
    __syncthreads();

    // self-zero the exact Ur/Vr/meta slices this block consumed (block-private,
    // after all reads above -> race-free). Restores the zero-invariant with no
    // extra kernel node. 8 wells x 16 floats = 32 float4 per rep per array.
    {
        float4 z4 = make_float4(0.f, 0.f, 0.f, 0.f);
#pragma unroll
        for (int r = 0; r < R; r++) {
            if (h < 32)
                ((float4*)(g_Ur + ((size_t)r * N_WELL + w0) * CF))[h] = z4;
            else if (h < 64)
                ((float4*)(g_Vr + ((size_t)r * N_WELL + w0) * CF))[h - 32] = z4;
            else if (h < 72)
                ((float4*)(g_meta + ((size_t)r * N_WELL + w0) * 4))[h - 64] = z4;
        }
    }

    float acc[WPB];
    {
        float f1 = g_F[32 * H + h], f2 = g_F[33 * H + h], f3 = g_F[42 * H + h];
#pragma unroll
        for (int t = 0; t < WPB; t++) acc[t] = f3 + sb1[t] * f1 + sb2[t] * f2;
    }
#pragma unroll
    for (int j = 0; j < CF; j++) {
        float m1 = g_F[j * H + h];
        float m2 = g_F[(16 + j) * H + h];
#pragma unroll
        for (int t = 0; t < WPB; t++) acc[t] += sUn[t][j] * m1 + sVn[t][j] * m2;
    }
#pragma unroll
    for (int j = 0; j < WF; j++) {
        float m3 = g_F[(34 + j) * H + h];
#pragma unroll
        for (int t = 0; t < WPB; t++) acc[t] += sWX[t][j] * m3;
    }
#pragma unroll
    for (int t = 0; t < WPB; t++) sm[h][t] = fmaxf(acc[t], 0.f);
    __syncthreads();

    if (h < OUT) {
        float o[WPB];
        float bv = __ldg(&bm2[h]);
#pragma unroll
        for (int t = 0; t < WPB; t++) o[t] = bv;
#pragma unroll 4
        for (int k = 0; k < H; k++) {
            float wm = __ldg(&Wm2[k * OUT + h]);
            float4 p0 = *(const float4*)&sm[k][0];
            float4 p1 = *(const float4*)&sm[k][4];
            o[0] += p0.x * wm;  o[1] += p0.y * wm;
            o[2] += p0.z * wm;  o[3] += p0.w * wm;
            o[4] += p1.x * wm;  o[5] += p1.y * wm;
            o[6] += p1.z * wm;  o[7] += p1.w * wm;
        }
#pragma unroll
        for (int t = 0; t < WPB; t++) out[(w0 + t) * OUT + h] = o[t];
    }
}

// ---------------- launch (6 kernel nodes, 4 events) ----------------
static cudaStream_t s1;
static cudaEvent_t evRoot, evV, evU, evEnd;
static bool g_host_init = false;

extern "C" void kernel_launch(void* const* d_in, const int* in_sizes, int n_in,
                              void* d_out, int out_size)
{
    if (!g_host_init) {
        cudaStreamCreateWithFlags(&s1, cudaStreamNonBlocking);
        cudaEventCreateWithFlags(&evRoot, cudaEventDisableTiming);
        cudaEventCreateWithFlags(&evV, cudaEventDisableTiming);
        cudaEventCreateWithFlags(&evU, cudaEventDisableTiming);
        cudaEventCreateWithFlags(&evEnd, cudaEventDisableTiming);
        g_host_init = true;
    }

    const float* cell_x  = (const float*)d_in[0];
    const float* well_x  = (const float*)d_in[1];
    const int*   ei_cell = (const int*)  d_in[2];
    const int*   ews     = (const int*)  d_in[3];
    const int*   ewd     = (const int*)  d_in[4];
    const float* W_cell  = (const float*)d_in[5];
    const float* b_cell  = (const float*)d_in[6];
    const float* W_well  = (const float*)d_in[7];
    const float* b_well  = (const float*)d_in[8];
    const float* Wl_cc   = (const float*)d_in[9];
    const float* bl_cc   = (const float*)d_in[10];
    const float* Wr_cc   = (const float*)d_in[11];
    const float* Wl_cw   = (const float*)d_in[12];
    const float* bl_cw   = (const float*)d_in[13];
    const float* Wr_cw   = (const float*)d_in[14];
    const float* W_m1    = (const float*)d_in[15];
    const float* b_m1    = (const float*)d_in[16];
    const float* W_m2    = (const float*)d_in[17];
    const float* b_m2    = (const float*)d_in[18];
    float* out = (float*)d_out;

    // fork
    cudaEventRecord(evRoot, 0);
    cudaStreamWaitEvent(s1, evRoot, 0);

    // side stream: combined fuse + cwV (scratch already zero at entry)
    k_side<<<43 + CWV_BLOCKS, 256, 0, s1>>>(
        W_cell, b_cell, Wl_cc, Wr_cc, bl_cc,
        W_well, b_well, Wl_cw, bl_cw, Wr_cw,
        W_m1, b_m1, ews, ewd, cell_x);
    cudaEventRecord(evV, s1);

    // main stream: mark -> cc -> cwU -> well(self-zeroing)
    k_mark<<<(E_CW + 255) / 256, 256>>>(ews);
    k_cc<<<(E_CC / 2 + 255) / 256, 256>>>(ei_cell, cell_x);
    cudaStreamWaitEvent(0, evV, 0);
    k_cwU<<<(E_CW / 2 + 255) / 256, 256>>>(ews, ewd);
    cudaEventRecord(evU, 0);                       // aggx/cnt fully consumed
    k_well<<<N_WELL / WPB, H>>>(well_x, W_m2, b_m2, out);

    // tail: restore aggx/cnt zero-invariant on side stream, overlapped with well
    cudaStreamWaitEvent(s1, evU, 0);
    k_zero_cell<<<(N_CELL * CF / 4 + 255) / 256, 256, 0, s1>>>();
    cudaEventRecord(evEnd, s1);
    cudaStreamWaitEvent(0, evEnd, 0);              // join for valid capture
}